// round 2
// baseline (speedup 1.0000x reference)
#include <cuda_runtime.h>
#include <cuda_bf16.h>
#include <stdint.h>

#define HID 128
#define MAX_NODES 50000

// Scratch (allocation-free rule: __device__ globals)
__device__ float g_x[MAX_NODES * HID];     // gemm output per layer
__device__ float g_acc[MAX_NODES * HID];   // segment-sum accumulator
__device__ float g_h0[MAX_NODES * HID];    // layer-0 hidden
__device__ float g_h1[MAX_NODES * HID];    // layer-1 hidden

// ---------------------------------------------------------------------------
// GEMM: out[M,128] = A[M,128] @ W[128,128]
// Block: 256 threads (8 warps). W fully in SMEM (64KB) + 64 staged A rows
// (32KB). Warp w owns rows w*8..w*8+7; lane owns cols lane*4..lane*4+3.
// ---------------------------------------------------------------------------
__global__ void __launch_bounds__(256, 2) gemm_kernel(
    const float* __restrict__ A, const float* __restrict__ W,
    float* __restrict__ out, int M)
{
    extern __shared__ float smem[];
    float* Wsh = smem;              // 128*128
    float* Ash = smem + HID * HID;  // 64*128

    int tid  = threadIdx.x;
    int warp = tid >> 5;
    int lane = tid & 31;

    // Load W (16384 floats / 256 threads = 64 each, coalesced)
    #pragma unroll
    for (int i = 0; i < 64; i++)
        Wsh[i * 256 + tid] = W[i * 256 + tid];

    int base = blockIdx.x * 64;

    // Stage 64 rows of A
    for (int i = tid; i < 64 * HID; i += 256) {
        int r = base + (i >> 7);
        Ash[i] = (r < M) ? A[r * HID + (i & 127)] : 0.0f;
    }
    __syncthreads();

    float acc[8][4];
    #pragma unroll
    for (int j = 0; j < 8; j++)
        #pragma unroll
        for (int q = 0; q < 4; q++) acc[j][q] = 0.0f;

    const float* arow = &Ash[(warp * 8) * HID];

    #pragma unroll 4
    for (int k = 0; k < HID; k++) {
        float4 wv = *(const float4*)&Wsh[k * HID + lane * 4];
        #pragma unroll
        for (int j = 0; j < 8; j++) {
            float a = arow[j * HID + k];
            acc[j][0] += a * wv.x;
            acc[j][1] += a * wv.y;
            acc[j][2] += a * wv.z;
            acc[j][3] += a * wv.w;
        }
    }

    #pragma unroll
    for (int j = 0; j < 8; j++) {
        int r = base + warp * 8 + j;
        if (r < M) {
            float4 v = make_float4(acc[j][0], acc[j][1], acc[j][2], acc[j][3]);
            *(float4*)&out[r * HID + lane * 4] = v;
        }
    }
}

// ---------------------------------------------------------------------------
// Zero the accumulator (float4 grid-stride)
// ---------------------------------------------------------------------------
__global__ void zero_kernel(float4* __restrict__ p, int n4)
{
    int i = blockIdx.x * blockDim.x + threadIdx.x;
    int stride = gridDim.x * blockDim.x;
    float4 z = make_float4(0.f, 0.f, 0.f, 0.f);
    for (; i < n4; i += stride) p[i] = z;
}

// ---------------------------------------------------------------------------
// Edge kernel: one warp per edge. lane handles 4 contiguous floats.
// msg = relu(x[src] + edge_attr[e]); red.add.v4 into acc[dst].
// edge_index is INT32 (jax x64 disabled): ei[0..E-1]=src, ei[E..2E-1]=dst.
// ---------------------------------------------------------------------------
__global__ void __launch_bounds__(256) edge_kernel(
    const float* __restrict__ x, const float* __restrict__ attr,
    const int* __restrict__ ei, float* __restrict__ acc, int E)
{
    int widx = (blockIdx.x * (blockDim.x >> 5)) + (threadIdx.x >> 5);
    if (widx >= E) return;
    int lane = threadIdx.x & 31;

    int s = ei[widx];
    int d = ei[E + widx];

    const float4 xv = *(const float4*)&x[(size_t)s * HID + lane * 4];
    const float4 av = *(const float4*)&attr[(size_t)widx * HID + lane * 4];

    float m0 = fmaxf(xv.x + av.x, 0.0f);
    float m1 = fmaxf(xv.y + av.y, 0.0f);
    float m2 = fmaxf(xv.z + av.z, 0.0f);
    float m3 = fmaxf(xv.w + av.w, 0.0f);

    float* dstp = &acc[(size_t)d * HID + lane * 4];
    asm volatile("red.global.add.v4.f32 [%0], {%1, %2, %3, %4};"
                 :: "l"(dstp), "f"(m0), "f"(m1), "f"(m2), "f"(m3)
                 : "memory");
}

// ---------------------------------------------------------------------------
// Node epilogue: hidden = acc + b; (relu if not last); hidden += cur
// ---------------------------------------------------------------------------
__global__ void node_kernel(
    const float4* __restrict__ acc, const float* __restrict__ bias,
    const float4* __restrict__ cur, float4* __restrict__ out,
    int n4, int do_relu)
{
    int i = blockIdx.x * blockDim.x + threadIdx.x;
    if (i >= n4) return;

    const float4 b4 = *(const float4*)&bias[(i & 31) * 4];  // 32 float4 per row
    float4 a = acc[i];
    float4 c = cur[i];

    float v0 = a.x + b4.x;
    float v1 = a.y + b4.y;
    float v2 = a.z + b4.z;
    float v3 = a.w + b4.w;
    if (do_relu) {
        v0 = fmaxf(v0, 0.f); v1 = fmaxf(v1, 0.f);
        v2 = fmaxf(v2, 0.f); v3 = fmaxf(v3, 0.f);
    }
    out[i] = make_float4(v0 + c.x, v1 + c.y, v2 + c.z, v3 + c.w);
}

// ---------------------------------------------------------------------------
// Host launcher
// ---------------------------------------------------------------------------
extern "C" void kernel_launch(void* const* d_in, const int* in_sizes, int n_in,
                              void* d_out, int out_size)
{
    const float* z    = (const float*)d_in[0];
    const int*   ei   = (const int*)d_in[1];     // int32 (jax x64 disabled)
    const float* attr = (const float*)d_in[2];
    const float* W    = (const float*)d_in[3];
    const float* b    = (const float*)d_in[4];
    float*       out  = (float*)d_out;

    const int N = in_sizes[0] / HID;       // 50000
    const int E = in_sizes[1] / 2;         // 600000

    float *x, *acc, *h0, *h1;
    cudaGetSymbolAddress((void**)&x,   g_x);
    cudaGetSymbolAddress((void**)&acc, g_acc);
    cudaGetSymbolAddress((void**)&h0,  g_h0);
    cudaGetSymbolAddress((void**)&h1,  g_h1);

    const int gemm_smem = (HID * HID + 64 * HID) * sizeof(float);
    cudaFuncSetAttribute(gemm_kernel,
                         cudaFuncAttributeMaxDynamicSharedMemorySize,
                         gemm_smem);

    const int gemm_grid  = (N + 63) / 64;
    const int n4         = N * HID / 4;
    const int node_grid  = (n4 + 255) / 256;
    const int edge_grid  = (E + 7) / 8;     // 8 warps/block, 1 warp/edge
    const int zero_grid  = 512;

    const float* cur = z;
    float* layer_out[3] = { h0, h1, out };

    for (int i = 0; i < 3; i++) {
        gemm_kernel<<<gemm_grid, 256, gemm_smem>>>(cur, W + i * HID * HID, x, N);
        zero_kernel<<<zero_grid, 256>>>((float4*)acc, n4);
        edge_kernel<<<edge_grid, 256>>>(x, attr, ei, acc, E);
        node_kernel<<<node_grid, 256>>>((const float4*)acc, b + i * HID,
                                        (const float4*)cur, (float4*)layer_out[i],
                                        n4, (i < 2) ? 1 : 0);
        cur = layer_out[i];
    }
}

// round 3
// speedup vs baseline: 1.1643x; 1.1643x over previous
#include <cuda_runtime.h>
#include <cuda_bf16.h>
#include <stdint.h>

#define HID 128
#define MAX_NODES 50000
#define MAX_EDGES 600000

// Scratch (allocation-free rule: __device__ globals)
__device__ float g_x[MAX_NODES * HID];       // gemm output per layer
__device__ float g_h0[MAX_NODES * HID];      // layer-0 hidden
__device__ float g_h1[MAX_NODES * HID];      // layer-1 hidden
__device__ int   g_cnt[MAX_NODES + 1];       // per-dst degree
__device__ int   g_off[MAX_NODES + 1];       // CSR row offsets
__device__ int   g_woff[MAX_NODES];          // scatter cursors
__device__ int2  g_es[MAX_EDGES];            // CSR payload: {edge_id, src}

// ---------------------------------------------------------------------------
// CSR build: zero counts -> histogram -> scan -> scatter
// ---------------------------------------------------------------------------
__global__ void zero_cnt_kernel(int* __restrict__ cnt, int n)
{
    int i = blockIdx.x * blockDim.x + threadIdx.x;
    if (i < n) cnt[i] = 0;
}

__global__ void hist_kernel(const int* __restrict__ ei, int* __restrict__ cnt, int E)
{
    int e = blockIdx.x * blockDim.x + threadIdx.x;
    if (e < E) atomicAdd(&cnt[ei[E + e]], 1);
}

// Single-block exclusive scan over N counts -> off (and woff copy), off[N]=E.
__global__ void __launch_bounds__(1024) scan_kernel(
    const int* __restrict__ cnt, int* __restrict__ off,
    int* __restrict__ woff, int N)
{
    __shared__ int sh[1024];
    int tid = threadIdx.x;
    int chunk = (N + 1023) / 1024;
    int start = tid * chunk;
    int end   = min(start + chunk, N);

    int s = 0;
    for (int i = start; i < end; i++) s += cnt[i];

    sh[tid] = s;
    __syncthreads();
    // Hillis-Steele inclusive scan
    #pragma unroll
    for (int d = 1; d < 1024; d <<= 1) {
        int v = (tid >= d) ? sh[tid - d] : 0;
        __syncthreads();
        sh[tid] += v;
        __syncthreads();
    }
    int run = sh[tid] - s;   // exclusive prefix for this chunk

    for (int i = start; i < end; i++) {
        off[i]  = run;
        woff[i] = run;
        run += cnt[i];
    }
    if (end == N && start <= N) off[N] = run;
}

__global__ void scatter_kernel(const int* __restrict__ ei,
                               int* __restrict__ woff,
                               int2* __restrict__ es, int E)
{
    int e = blockIdx.x * blockDim.x + threadIdx.x;
    if (e >= E) return;
    int s = ei[e];
    int d = ei[E + e];
    int pos = atomicAdd(&woff[d], 1);
    es[pos] = make_int2(e, s);
}

// ---------------------------------------------------------------------------
// GEMM: out[M,128] = A[M,128] @ W[128,128] using packed fma.rn.f32x2.
// 256 threads / 8 warps. W in SMEM (64KB) + 64 A rows (32KB).
// Warp w owns rows w*8..w*8+7; lane owns cols lane*4..lane*4+3 (2 f32x2 pairs).
// ---------------------------------------------------------------------------
__global__ void __launch_bounds__(256, 2) gemm_kernel(
    const float* __restrict__ A, const float* __restrict__ W,
    float* __restrict__ out, int M)
{
    extern __shared__ float smem[];
    float* Wsh = smem;              // 128*128
    float* Ash = smem + HID * HID;  // 64*128

    int tid  = threadIdx.x;
    int warp = tid >> 5;
    int lane = tid & 31;

    #pragma unroll
    for (int i = 0; i < 64; i++)
        Wsh[i * 256 + tid] = W[i * 256 + tid];

    int base = blockIdx.x * 64;
    for (int i = tid; i < 64 * HID; i += 256) {
        int r = base + (i >> 7);
        Ash[i] = (r < M) ? A[r * HID + (i & 127)] : 0.0f;
    }
    __syncthreads();

    unsigned long long acc2[8][2];
    #pragma unroll
    for (int j = 0; j < 8; j++) { acc2[j][0] = 0ULL; acc2[j][1] = 0ULL; }

    const float* arow = &Ash[(warp * 8) * HID];

    #pragma unroll 4
    for (int k = 0; k < HID; k++) {
        ulonglong2 wv = *(const ulonglong2*)&Wsh[k * HID + lane * 4];
        #pragma unroll
        for (int j = 0; j < 8; j++) {
            float a = arow[j * HID + k];
            unsigned long long ap;
            asm("mov.b64 %0, {%1, %1};" : "=l"(ap) : "f"(a));
            asm("fma.rn.f32x2 %0, %1, %2, %0;" : "+l"(acc2[j][0]) : "l"(ap), "l"(wv.x));
            asm("fma.rn.f32x2 %0, %1, %2, %0;" : "+l"(acc2[j][1]) : "l"(ap), "l"(wv.y));
        }
    }

    #pragma unroll
    for (int j = 0; j < 8; j++) {
        int r = base + warp * 8 + j;
        if (r < M) {
            float4 v;
            asm("mov.b64 {%0, %1}, %2;" : "=f"(v.x), "=f"(v.y) : "l"(acc2[j][0]));
            asm("mov.b64 {%0, %1}, %2;" : "=f"(v.z), "=f"(v.w) : "l"(acc2[j][1]));
            *(float4*)&out[r * HID + lane * 4] = v;
        }
    }
}

// ---------------------------------------------------------------------------
// Fused gather: one warp per dst node. Walk CSR edges, accumulate
// relu(x[src] + attr[e]) in registers, then bias (+relu) + residual -> out.
// attr is streamed once -> __ldcs (evict-first) to protect L2-resident x.
// ---------------------------------------------------------------------------
__global__ void __launch_bounds__(256) gather_kernel(
    const float* __restrict__ x, const float* __restrict__ attr,
    const int* __restrict__ off, const int2* __restrict__ es,
    const float* __restrict__ bias, const float* __restrict__ cur,
    float* __restrict__ out, int N, int do_relu)
{
    int node = (blockIdx.x * (blockDim.x >> 5)) + (threadIdx.x >> 5);
    if (node >= N) return;
    int lane = threadIdx.x & 31;

    int o0 = off[node];
    int deg = off[node + 1] - o0;

    float a0 = 0.f, a1 = 0.f, a2 = 0.f, a3 = 0.f;

    int2 nxt = (deg > 0) ? es[o0] : make_int2(0, 0);
    for (int i = 0; i < deg; i++) {
        int2 e = nxt;
        if (i + 1 < deg) nxt = es[o0 + i + 1];

        const float4 xv = *(const float4*)&x[(size_t)e.y * HID + lane * 4];
        const float4 av = __ldcs((const float4*)&attr[(size_t)e.x * HID + lane * 4]);

        a0 += fmaxf(xv.x + av.x, 0.0f);
        a1 += fmaxf(xv.y + av.y, 0.0f);
        a2 += fmaxf(xv.z + av.z, 0.0f);
        a3 += fmaxf(xv.w + av.w, 0.0f);
    }

    const float4 b4 = *(const float4*)&bias[lane * 4];
    float v0 = a0 + b4.x, v1 = a1 + b4.y, v2 = a2 + b4.z, v3 = a3 + b4.w;
    if (do_relu) {
        v0 = fmaxf(v0, 0.f); v1 = fmaxf(v1, 0.f);
        v2 = fmaxf(v2, 0.f); v3 = fmaxf(v3, 0.f);
    }
    const float4 c4 = *(const float4*)&cur[(size_t)node * HID + lane * 4];
    *(float4*)&out[(size_t)node * HID + lane * 4] =
        make_float4(v0 + c4.x, v1 + c4.y, v2 + c4.z, v3 + c4.w);
}

// ---------------------------------------------------------------------------
// Host launcher
// ---------------------------------------------------------------------------
extern "C" void kernel_launch(void* const* d_in, const int* in_sizes, int n_in,
                              void* d_out, int out_size)
{
    const float* z    = (const float*)d_in[0];
    const int*   ei   = (const int*)d_in[1];     // int32 (jax x64 disabled)
    const float* attr = (const float*)d_in[2];
    const float* W    = (const float*)d_in[3];
    const float* b    = (const float*)d_in[4];
    float*       out  = (float*)d_out;

    const int N = in_sizes[0] / HID;       // 50000
    const int E = in_sizes[1] / 2;         // 600000

    float *x, *h0, *h1;
    int *cnt, *off, *woff;
    int2 *es;
    cudaGetSymbolAddress((void**)&x,    g_x);
    cudaGetSymbolAddress((void**)&h0,   g_h0);
    cudaGetSymbolAddress((void**)&h1,   g_h1);
    cudaGetSymbolAddress((void**)&cnt,  g_cnt);
    cudaGetSymbolAddress((void**)&off,  g_off);
    cudaGetSymbolAddress((void**)&woff, g_woff);
    cudaGetSymbolAddress((void**)&es,   g_es);

    const int gemm_smem = (HID * HID + 64 * HID) * sizeof(float);
    cudaFuncSetAttribute(gemm_kernel,
                         cudaFuncAttributeMaxDynamicSharedMemorySize,
                         gemm_smem);

    // CSR build (per replay; edge_index is an input)
    zero_cnt_kernel<<<(N + 256) / 256, 256>>>(cnt, N + 1);
    hist_kernel<<<(E + 255) / 256, 256>>>(ei, cnt, E);
    scan_kernel<<<1, 1024>>>(cnt, off, woff, N);
    scatter_kernel<<<(E + 255) / 256, 256>>>(ei, woff, es, E);

    const int gemm_grid   = (N + 63) / 64;
    const int gather_grid = (N + 7) / 8;    // 8 warps/block, 1 warp/node

    const float* cur = z;
    float* layer_out[3] = { h0, h1, out };

    for (int i = 0; i < 3; i++) {
        gemm_kernel<<<gemm_grid, 256, gemm_smem>>>(cur, W + i * HID * HID, x, N);
        gather_kernel<<<gather_grid, 256>>>(x, attr, off, es,
                                            b + i * HID, cur, layer_out[i],
                                            N, (i < 2) ? 1 : 0);
        cur = layer_out[i];
    }
}